// round 4
// baseline (speedup 1.0000x reference)
#include <cuda_runtime.h>
#include <cstdint>

// out[n, :] = weight[idx_n, :] where one_hot[n, idx_n] == 1.0
// N = 8192 rows, VOCAB = 8192, D = 1024. All fp32.
//
// Strategy: warp-per-row. Phase 1: scan the one-hot row 512 floats per
// iteration (4x float4 per lane) with early exit via ballot. Phase 2: the
// same warp copies the 4KB weight row to the output.

#define N_ROWS 8192
#define VOCAB  8192
#define DIM    1024
#define WARPS_PER_BLOCK 8
#define THREADS (WARPS_PER_BLOCK * 32)

__global__ __launch_bounds__(THREADS) void onehot_gather_kernel(
    const float* __restrict__ one_hot,
    const float* __restrict__ weight,
    float* __restrict__ out)
{
    const int warp_global = (blockIdx.x * blockDim.x + threadIdx.x) >> 5;
    const int lane = threadIdx.x & 31;
    if (warp_global >= N_ROWS) return;

    const float4* __restrict__ row =
        reinterpret_cast<const float4*>(one_hot + (size_t)warp_global * VOCAB);

    // VOCAB/4 = 2048 float4 per row. Per iteration each lane loads 4 float4
    // at stride 32: covers 512 floats (128 float4). 16 iterations max.
    int idx = -1;
    #pragma unroll 1
    for (int base = 0; base < VOCAB / 4; base += 128) {
        float4 v0 = row[base + lane];
        float4 v1 = row[base + 32 + lane];
        float4 v2 = row[base + 64 + lane];
        float4 v3 = row[base + 96 + lane];

        bool nz0 = (v0.x != 0.f) || (v0.y != 0.f) || (v0.z != 0.f) || (v0.w != 0.f);
        bool nz1 = (v1.x != 0.f) || (v1.y != 0.f) || (v1.z != 0.f) || (v1.w != 0.f);
        bool nz2 = (v2.x != 0.f) || (v2.y != 0.f) || (v2.z != 0.f) || (v2.w != 0.f);
        bool nz3 = (v3.x != 0.f) || (v3.y != 0.f) || (v3.z != 0.f) || (v3.w != 0.f);

        unsigned m = __ballot_sync(0xFFFFFFFFu, nz0 || nz1 || nz2 || nz3);
        if (m) {
            int src = __ffs(m) - 1;
            int my_idx = -1;
            if (lane == src) {
                // which of my 4 chunks, and which element within it
                float4 v; int chunk;
                if (nz0)      { v = v0; chunk = 0; }
                else if (nz1) { v = v1; chunk = 1; }
                else if (nz2) { v = v2; chunk = 2; }
                else          { v = v3; chunk = 3; }
                int e = (v.x != 0.f) ? 0 : (v.y != 0.f) ? 1 : (v.z != 0.f) ? 2 : 3;
                my_idx = (base + chunk * 32 + lane) * 4 + e;
            }
            idx = __shfl_sync(0xFFFFFFFFu, my_idx, src);
            break;
        }
    }

    // Defensive: all-zero row (shouldn't happen for a true one-hot) -> zeros.
    if (idx < 0) {
        float4 z = make_float4(0.f, 0.f, 0.f, 0.f);
        float4* __restrict__ orow =
            reinterpret_cast<float4*>(out + (size_t)warp_global * DIM);
        #pragma unroll
        for (int i = 0; i < DIM / 4 / 32; i++)
            orow[i * 32 + lane] = z;
        return;
    }

    // Phase 2: copy weight[idx, :] (4KB) to out[row, :]
    const float4* __restrict__ wrow =
        reinterpret_cast<const float4*>(weight + (size_t)idx * DIM);
    float4* __restrict__ orow =
        reinterpret_cast<float4*>(out + (size_t)warp_global * DIM);

    #pragma unroll
    for (int i = 0; i < DIM / 4 / 32; i++)   // 8 iterations
        orow[i * 32 + lane] = wrow[i * 32 + lane];
}

extern "C" void kernel_launch(void* const* d_in, const int* in_sizes, int n_in,
                              void* d_out, int out_size)
{
    const float* one_hot = (const float*)d_in[0];  // [N, VOCAB] fp32
    const float* weight  = (const float*)d_in[1];  // [VOCAB, D] fp32
    float* out = (float*)d_out;                    // [N, D] fp32

    const int total_warps = N_ROWS;
    const int blocks = (total_warps + WARPS_PER_BLOCK - 1) / WARPS_PER_BLOCK;
    onehot_gather_kernel<<<blocks, THREADS>>>(one_hot, weight, out);
}